// round 17
// baseline (speedup 1.0000x reference)
#include <cuda_runtime.h>
#include <cuda_fp16.h>
#include <cstdint>

#define BATCH 8
#define LQ 2048
#define LY 2048
#define DIM 64
#define EPSN 1e-8f

#define RS 72                    // tile row stride in halves (144 B)
#define TILE_HB (128 * RS * 2)   // 18432 B per tile
#define SM_TOTAL (3 * TILE_HB)   // A + 2 B tiles = 55296 B dynamic smem

// fp16 normalized operands (input quant ~2.9e-4; +fp16 acc -> 4.4e-4 measured)
__device__ __half g_q[(size_t)BATCH * LQ * DIM];
__device__ __half g_y[(size_t)BATCH * LY * DIM];

__device__ __forceinline__ uint32_t smem_u32(const void* p) {
    uint32_t a;
    asm("{ .reg .u64 t; cvta.to.shared.u64 t, %1; cvt.u32.u64 %0, t; }"
        : "=r"(a) : "l"(p));
    return a;
}
__device__ __forceinline__ void atomicMaxFloat(float* addr, float v) {
    if (v >= 0.0f)
        atomicMax((int*)addr, __float_as_int(v));
    else
        atomicMin((unsigned int*)addr, __float_as_uint(v));
}

#define LDSM_X4(r0, r1, r2, r3, addr)                                          \
    asm volatile("ldmatrix.sync.aligned.m8n8.x4.shared.b16 {%0,%1,%2,%3}, [%4];" \
                 : "=r"(r0), "=r"(r1), "=r"(r2), "=r"(r3) : "r"(addr))

// fp16-accumulator MMA: D/C are 2 packed half2 regs (rows l>>2 and l>>2+8).
#define MMA_F16ACC(d, a, bf)                                                   \
    asm volatile(                                                              \
        "mma.sync.aligned.m16n8k16.row.col.f16.f16.f16.f16 "                  \
        "{%0,%1}, {%2,%3,%4,%5}, {%6,%7}, {%0,%1};"                           \
        : "+r"(d[0]), "+r"(d[1])                                               \
        : "r"(a[0]), "r"(a[1]), "r"(a[2]), "r"(a[3]), "r"(bf[0]), "r"(bf[1]))

#define CP_ASYNC_CG16(smaddr, gptr)                                            \
    asm volatile("cp.async.cg.shared.global [%0], [%1], 16;"                    \
                 :: "r"(smaddr), "l"(gptr))

// y-column permutation within each 64-row B group: output col c -> MMA slot.
__device__ __forceinline__ int bperm(int c) {
    return (c & 48) + ((c & 2) << 2) + ((c & 12) >> 1) + (c & 1);
}

// ---------------------------------------------------------------------------
// Prep: normalize -> fp16. 4 rows per warp. Also inits sim on q rows.
// ---------------------------------------------------------------------------
__global__ void prep_kernel(const float* __restrict__ q,
                            const float* __restrict__ y,
                            float* __restrict__ sim) {
    int gw   = (blockIdx.x * blockDim.x + threadIdx.x) >> 5;
    int lane = threadIdx.x & 31;
    int r    = gw * 4 + (lane >> 3);
    int j    = lane & 7;
    const int rows = BATCH * LQ;
    if (r >= 2 * rows) return;
    bool isQ = r < rows;
    int row  = isQ ? r : r - rows;

    const float4* src = (const float4*)((isQ ? q : y) + (size_t)row * DIM);
    float4 v1 = src[j * 2];
    float4 v2 = src[j * 2 + 1];
    float ss = v1.x * v1.x + v1.y * v1.y + v1.z * v1.z + v1.w * v1.w +
               v2.x * v2.x + v2.y * v2.y + v2.z * v2.z + v2.w * v2.w;
    ss += __shfl_xor_sync(0xffffffffu, ss, 1);
    ss += __shfl_xor_sync(0xffffffffu, ss, 2);
    ss += __shfl_xor_sync(0xffffffffu, ss, 4);
    float inv = 1.0f / fmaxf(sqrtf(ss), EPSN);

    __half2 h[4];
    h[0] = __floats2half2_rn(v1.x * inv, v1.y * inv);
    h[1] = __floats2half2_rn(v1.z * inv, v1.w * inv);
    h[2] = __floats2half2_rn(v2.x * inv, v2.y * inv);
    h[3] = __floats2half2_rn(v2.z * inv, v2.w * inv);
    __half* dst = (isQ ? g_q : g_y) + (size_t)row * DIM + j * 8;
    *(uint4*)dst = *(uint4*)h;
    if (isQ && j == 0) sim[row] = __int_as_float(0xff800000);
}

// ---------------------------------------------------------------------------
// HMMA GEMM: CTA = 128(q) x 256(y) supertile, 8 warps (4x2), warp 32x64/tile,
// fp16 accumulators, 3 CTAs/SM. Permuted-B STG.128 epilogue via __stwt
// (write-through: no L2 dirty-eviction traffic). Split cp.async wait groups.
// ---------------------------------------------------------------------------
__global__ __launch_bounds__(256, 3)
void gemm_kernel(float* __restrict__ att, float* __restrict__ sim) {
    extern __shared__ char smem[];
    const uint32_t smA = smem_u32(smem);
    const uint32_t smB = smA + TILE_HB;

    const int tid  = threadIdx.x;
    const int lane = tid & 31;
    const int wid  = tid >> 5;
    const int wm   = wid & 3;    // q group (32 rows)
    const int wn   = wid >> 2;   // y group (64 cols)

    const int b   = blockIdx.z;
    const int yt0 = blockIdx.x * 256;
    const int qt  = blockIdx.y * 128;

    // --- async fills: group1 = A + B0, group0 = B1 (permuted rows) ---
    const float4* qsrc = (const float4*)(g_q + ((size_t)b * LQ + qt) * DIM);
    const float4* ysrc = (const float4*)(g_y + ((size_t)b * LY + yt0) * DIM);
#pragma unroll
    for (int it = 0; it < 4; it++) {
        int idx = it * 256 + tid;
        int row = idx >> 3, c = idx & 7;
        CP_ASYNC_CG16(smA + row * (RS * 2) + c * 16, qsrc + idx);
    }
#pragma unroll
    for (int it = 0; it < 4; it++) {                 // B0: rows 0..127
        int idx = it * 256 + tid;
        int n = idx >> 3, c = idx & 7;
        int rowp = (n & ~63) + bperm(n & 63);
        CP_ASYNC_CG16(smB + rowp * (RS * 2) + c * 16, ysrc + idx);
    }
    asm volatile("cp.async.commit_group;" ::: "memory");
#pragma unroll
    for (int it = 4; it < 8; it++) {                 // B1: rows 128..255
        int idx = it * 256 + tid;
        int n = idx >> 3, c = idx & 7;
        int rowp = (n & ~63) + bperm(n & 63);
        CP_ASYNC_CG16(smB + rowp * (RS * 2) + c * 16, ysrc + idx);
    }
    asm volatile("cp.async.commit_group;" ::: "memory");

    uint32_t aaddr[2];
#pragma unroll
    for (int mi = 0; mi < 2; mi++) {
        int row = wm * 32 + mi * 16 + (lane & 15);
        aaddr[mi] = smA + row * (RS * 2) + ((lane >> 4) & 1) * 16;
    }
    uint32_t baddr[4];
#pragma unroll
    for (int np = 0; np < 4; np++) {
        int n = wn * 64 + np * 16 + (lane & 7) + ((lane >> 4) & 1) * 8;
        baddr[np] = smB + n * (RS * 2) + ((lane >> 3) & 1) * 16;
    }

    const int qlane = lane >> 2;
    const int npair = lane & 3;

#pragma unroll
    for (int t = 0; t < 2; t++) {
        // t=0: wait for A+B0 only (B1 still in flight); t=1: wait all.
        if (t == 0)
            asm volatile("cp.async.wait_group 1;" ::: "memory");
        else
            asm volatile("cp.async.wait_group 0;" ::: "memory");
        __syncthreads();

        const uint32_t bB = t * TILE_HB;
        uint32_t acc[2][8][2];   // packed half2 accumulators (32 regs)
#pragma unroll
        for (int mi = 0; mi < 2; mi++)
#pragma unroll
            for (int ni = 0; ni < 8; ni++) {
                acc[mi][ni][0] = 0u;
                acc[mi][ni][1] = 0u;
            }

#pragma unroll
        for (int ks = 0; ks < 4; ks++) {
            uint32_t bf[8][2];
#pragma unroll
            for (int np = 0; np < 4; np++)
                LDSM_X4(bf[2 * np][0], bf[2 * np][1], bf[2 * np + 1][0],
                        bf[2 * np + 1][1], baddr[np] + bB + ks * 32);
            uint32_t a[2][4];
#pragma unroll
            for (int mi = 0; mi < 2; mi++)
                LDSM_X4(a[mi][0], a[mi][1], a[mi][2], a[mi][3],
                        aaddr[mi] + ks * 32);
#pragma unroll
            for (int mi = 0; mi < 2; mi++)
#pragma unroll
                for (int ni = 0; ni < 8; ni++)
                    MMA_F16ACC(acc[mi][ni], a[mi], bf[ni]);
        }

        // --- Epilogue: write-through STG.128 (permuted ownership) + max ---
        const int yt = yt0 + t * 128;
#pragma unroll
        for (int mi = 0; mi < 2; mi++) {
#pragma unroll
            for (int h = 0; h < 2; h++) {
                int qrow = qt + wm * 32 + mi * 16 + h * 8 + qlane;
                float* outrow =
                    att + ((size_t)b * LQ + qrow) * LY + yt + wn * 64;

                __half2 hm = __halves2half2(__ushort_as_half(0xFC00),
                                            __ushort_as_half(0xFC00));
#pragma unroll
                for (int ni = 0; ni < 8; ni++)
                    hm = __hmax2(hm, *(__half2*)&acc[mi][ni][h]);
                float m = fmaxf(__half2float(__low2half(hm)),
                                __half2float(__high2half(hm)));
                m = fmaxf(m, __shfl_xor_sync(0xffffffffu, m, 1));
                m = fmaxf(m, __shfl_xor_sync(0xffffffffu, m, 2));
                if (npair == 0)
                    atomicMaxFloat(&sim[(size_t)b * LQ + qrow], m);

#pragma unroll
                for (int k = 0; k < 4; k++) {
                    float2 f2 = __half22float2(*(__half2*)&acc[mi][2 * k][h]);
                    float2 g2 =
                        __half22float2(*(__half2*)&acc[mi][2 * k + 1][h]);
                    __stwt((float4*)(outrow + 16 * k + 4 * npair),
                           make_float4(f2.x, f2.y, g2.x, g2.y));
                }
            }
        }
    }
}

// ---------------------------------------------------------------------------
extern "C" void kernel_launch(void* const* d_in, const int* in_sizes, int n_in,
                              void* d_out, int out_size) {
    const float* q = (const float*)d_in[0];
    const float* y = (const float*)d_in[1];
    float* att = (float*)d_out;
    float* sim = att + (size_t)BATCH * LQ * LY;

    static bool attr_done = false;
    if (!attr_done) {
        cudaFuncSetAttribute(gemm_kernel,
                             cudaFuncAttributeMaxDynamicSharedMemorySize,
                             SM_TOTAL);
        attr_done = true;
    }

    int warps = (2 * BATCH * LQ) / 4;
    prep_kernel<<<(warps * 32 + 255) / 256, 256>>>(q, y, sim);

    dim3 grid(LY / 256, LQ / 128, BATCH);   // (8, 16, 8) = 1024 CTAs
    gemm_kernel<<<grid, 256, SM_TOTAL>>>(att, sim);
}